// round 5
// baseline (speedup 1.0000x reference)
#include <cuda_runtime.h>
#include <cstdint>

#define NN 100000
#define NE 1600000
#define IN_CH 64
#define HID 64
#define N_CLS 40

// Scratch (allocation-free contract: __device__ globals).
__device__ float4 g_Y4 [(size_t)NN * (HID / 4)];
__device__ float4 g_H14[(size_t)NN * (HID / 4)];
__device__ float4 g_Z4 [(size_t)NN * (HID / 4)];
__device__ int    g_cnt [NN];      // in-degree histogram
__device__ int    g_ptr [NN + 1];  // CSR row pointers (grouped by dst)
__device__ int    g_woff[NN];      // working offsets for CSR fill
__device__ int    g_csrc[NE];      // src node per edge, grouped by dst

// ---------------------------------------------------------------------------
// Zero the histogram
// ---------------------------------------------------------------------------
__global__ void __launch_bounds__(256) zero_cnt_kernel(int n) {
    int t = blockIdx.x * blockDim.x + threadIdx.x;
    if (t < n) g_cnt[t] = 0;
}

// ---------------------------------------------------------------------------
// Histogram of dst indices
// ---------------------------------------------------------------------------
__global__ void __launch_bounds__(256) hist_kernel(const int* __restrict__ ei, int E) {
    int e = blockIdx.x * blockDim.x + threadIdx.x;
    if (e < E) atomicAdd(&g_cnt[__ldg(ei + E + e)], 1);
}

// ---------------------------------------------------------------------------
// Single-block exclusive scan of g_cnt -> g_ptr (and g_woff copy), g_ptr[n]=E
// ---------------------------------------------------------------------------
__global__ void __launch_bounds__(1024) scan_kernel(int n) {
    __shared__ int sh[1024];
    int tid = threadIdx.x;
    int chunk = (n + 1023) / 1024;
    int begin = tid * chunk;
    int end = min(begin + chunk, n);

    int s = 0;
    for (int i = begin; i < end; i++) s += g_cnt[i];

    // Hillis–Steele inclusive scan over the 1024 per-thread sums
    sh[tid] = s;
    __syncthreads();
    for (int off = 1; off < 1024; off <<= 1) {
        int v = (tid >= off) ? sh[tid - off] : 0;
        __syncthreads();
        sh[tid] += v;
        __syncthreads();
    }
    int run = sh[tid] - s;  // exclusive prefix for this chunk

    for (int i = begin; i < end; i++) {
        g_ptr[i] = run;
        g_woff[i] = run;
        run += g_cnt[i];
    }
    if (tid == 1023) g_ptr[n] = run;  // == E
}

// ---------------------------------------------------------------------------
// CSR fill: slot per (dst) via atomic bump; store src
// ---------------------------------------------------------------------------
__global__ void __launch_bounds__(256) fill_kernel(const int* __restrict__ ei, int E) {
    int e = blockIdx.x * blockDim.x + threadIdx.x;
    if (e >= E) return;
    int s = __ldg(ei + e);
    int d = __ldg(ei + E + e);
    int pos = atomicAdd(&g_woff[d], 1);
    g_csrc[pos] = s;
}

// ---------------------------------------------------------------------------
// Dense layer 1: Y = relu(NF @ W1 + b1), thread-per-row, W1 in smem
// ---------------------------------------------------------------------------
__global__ void __launch_bounds__(256) dense1_kernel(
    const float* __restrict__ nf, const float* __restrict__ W1,
    const float* __restrict__ b1, int n)
{
    __shared__ float Ws[IN_CH * HID];
    __shared__ float bs[HID];
    for (int i = threadIdx.x; i < IN_CH * HID; i += blockDim.x) Ws[i] = W1[i];
    for (int i = threadIdx.x; i < HID; i += blockDim.x) bs[i] = b1[i];
    __syncthreads();

    int row = blockIdx.x * blockDim.x + threadIdx.x;
    if (row >= n) return;

    float x[IN_CH];
    const float4* xr = reinterpret_cast<const float4*>(nf + (size_t)row * IN_CH);
    #pragma unroll
    for (int k4 = 0; k4 < IN_CH / 4; k4++) {
        float4 v = xr[k4];
        x[4*k4+0] = v.x; x[4*k4+1] = v.y; x[4*k4+2] = v.z; x[4*k4+3] = v.w;
    }

    float4* yr = g_Y4 + (size_t)row * (HID / 4);
    #pragma unroll 1
    for (int jj = 0; jj < HID / 4; jj++) {
        float4 acc = *reinterpret_cast<const float4*>(bs + jj * 4);
        #pragma unroll
        for (int k = 0; k < IN_CH; k++) {
            float4 w = *reinterpret_cast<const float4*>(Ws + k * HID + jj * 4);
            acc.x = fmaf(x[k], w.x, acc.x);
            acc.y = fmaf(x[k], w.y, acc.y);
            acc.z = fmaf(x[k], w.z, acc.z);
            acc.w = fmaf(x[k], w.w, acc.w);
        }
        acc.x = fmaxf(acc.x, 0.f); acc.y = fmaxf(acc.y, 0.f);
        acc.z = fmaxf(acc.z, 0.f); acc.w = fmaxf(acc.w, 0.f);
        yr[jj] = acc;
    }
}

// ---------------------------------------------------------------------------
// Gather-side aggregation: dst[i] = sum over in-edges of src_tab[csrc[e]].
// One warp per node. Half-warp split processes 2 edges/iteration; lanes 0-15
// and 16-31 hold partial float4 sums for chunks c=lane&15, combined by
// shfl_xor(16). Writes each output row exactly once — no atomics, no zeroing.
// PASS==0: Y -> H1;  PASS==1: H1 -> Z
// ---------------------------------------------------------------------------
template <int PASS>
__global__ void __launch_bounds__(256) agg_kernel(int n)
{
    int warp = (blockIdx.x * blockDim.x + threadIdx.x) >> 5;
    if (warp >= n) return;
    int lane = threadIdx.x & 31;
    int half = lane >> 4;
    int c    = lane & 15;

    int beg = __ldg(&g_ptr[warp]);
    int endp = __ldg(&g_ptr[warp + 1]);

    const float4* srct = (PASS == 0) ? g_Y4  : g_H14;
    float4*       dstt = (PASS == 0) ? g_H14 : g_Z4;

    float4 acc = make_float4(0.f, 0.f, 0.f, 0.f);

    int e = beg + half;
    // unrolled by 2 (4 edges in flight per warp) for MLP
    for (; e + 2 < endp; e += 4) {
        int s0 = __ldg(&g_csrc[e]);
        int s1 = __ldg(&g_csrc[e + 2]);
        float4 v0 = __ldg(&srct[(size_t)s0 * (HID / 4) + c]);
        float4 v1 = __ldg(&srct[(size_t)s1 * (HID / 4) + c]);
        acc.x += v0.x + v1.x; acc.y += v0.y + v1.y;
        acc.z += v0.z + v1.z; acc.w += v0.w + v1.w;
    }
    if (e < endp) {
        int s0 = __ldg(&g_csrc[e]);
        float4 v0 = __ldg(&srct[(size_t)s0 * (HID / 4) + c]);
        acc.x += v0.x; acc.y += v0.y; acc.z += v0.z; acc.w += v0.w;
    }

    // combine the two half-warp partials
    acc.x += __shfl_xor_sync(0xffffffffu, acc.x, 16);
    acc.y += __shfl_xor_sync(0xffffffffu, acc.y, 16);
    acc.z += __shfl_xor_sync(0xffffffffu, acc.z, 16);
    acc.w += __shfl_xor_sync(0xffffffffu, acc.w, 16);

    if (half == 0) dstt[(size_t)warp * (HID / 4) + c] = acc;
}

// ---------------------------------------------------------------------------
// Fused dense tail: h2 = Z@W2 + deg*b2; logits = h2@Wf + bf; softmax -> out
// deg comes free from CSR: ptr[i+1]-ptr[i]
// ---------------------------------------------------------------------------
__global__ void __launch_bounds__(128) dense2_kernel(
    const float* __restrict__ W2, const float* __restrict__ b2,
    const float* __restrict__ Wf, const float* __restrict__ bf,
    float* __restrict__ out, int n)
{
    __shared__ float W2s[HID * HID];
    __shared__ float Wfs[HID * N_CLS];
    __shared__ float b2s[HID];
    __shared__ float bfs[N_CLS];
    for (int i = threadIdx.x; i < HID * HID; i += blockDim.x) W2s[i] = W2[i];
    for (int i = threadIdx.x; i < HID * N_CLS; i += blockDim.x) Wfs[i] = Wf[i];
    for (int i = threadIdx.x; i < HID; i += blockDim.x) b2s[i] = b2[i];
    for (int i = threadIdx.x; i < N_CLS; i += blockDim.x) bfs[i] = bf[i];
    __syncthreads();

    int row = blockIdx.x * blockDim.x + threadIdx.x;
    if (row >= n) return;

    float z[HID];
    const float4* zr = g_Z4 + (size_t)row * (HID / 4);
    #pragma unroll
    for (int k4 = 0; k4 < HID / 4; k4++) {
        float4 v = zr[k4];
        z[4*k4+0] = v.x; z[4*k4+1] = v.y; z[4*k4+2] = v.z; z[4*k4+3] = v.w;
    }
    float degf = (float)(__ldg(&g_ptr[row + 1]) - __ldg(&g_ptr[row]));

    float logits[N_CLS];
    #pragma unroll
    for (int cc = 0; cc < N_CLS; cc++) logits[cc] = bfs[cc];

    #pragma unroll 1
    for (int jj = 0; jj < HID / 4; jj++) {
        float h[4];
        #pragma unroll
        for (int u = 0; u < 4; u++) h[u] = degf * b2s[jj * 4 + u];
        #pragma unroll
        for (int k = 0; k < HID; k++) {
            float4 w = *reinterpret_cast<const float4*>(W2s + k * HID + jj * 4);
            h[0] = fmaf(z[k], w.x, h[0]);
            h[1] = fmaf(z[k], w.y, h[1]);
            h[2] = fmaf(z[k], w.z, h[2]);
            h[3] = fmaf(z[k], w.w, h[3]);
        }
        #pragma unroll
        for (int u = 0; u < 4; u++) {
            int j = jj * 4 + u;
            #pragma unroll
            for (int c4 = 0; c4 < N_CLS / 4; c4++) {
                float4 w = *reinterpret_cast<const float4*>(Wfs + j * N_CLS + c4 * 4);
                logits[c4*4+0] = fmaf(h[u], w.x, logits[c4*4+0]);
                logits[c4*4+1] = fmaf(h[u], w.y, logits[c4*4+1]);
                logits[c4*4+2] = fmaf(h[u], w.z, logits[c4*4+2]);
                logits[c4*4+3] = fmaf(h[u], w.w, logits[c4*4+3]);
            }
        }
    }

    // softmax over N_CLS
    float m = logits[0];
    #pragma unroll
    for (int cc = 1; cc < N_CLS; cc++) m = fmaxf(m, logits[cc]);
    float ssum = 0.f;
    #pragma unroll
    for (int cc = 0; cc < N_CLS; cc++) {
        float ev = __expf(logits[cc] - m);
        logits[cc] = ev;
        ssum += ev;
    }
    float inv = 1.f / ssum;
    float* orow = out + (size_t)row * N_CLS;
    #pragma unroll
    for (int c4 = 0; c4 < N_CLS / 4; c4++) {
        float4 o;
        o.x = logits[c4*4+0] * inv; o.y = logits[c4*4+1] * inv;
        o.z = logits[c4*4+2] * inv; o.w = logits[c4*4+3] * inv;
        *reinterpret_cast<float4*>(orow + c4 * 4) = o;
    }
}

// ---------------------------------------------------------------------------
extern "C" void kernel_launch(void* const* d_in, const int* in_sizes, int n_in,
                              void* d_out, int out_size)
{
    const float* nf = (const float*)d_in[0];
    const int*   ei = (const int*)d_in[1];   // int32 (JAX x64 disabled)
    const float* W1 = (const float*)d_in[2];
    const float* b1 = (const float*)d_in[3];
    const float* W2 = (const float*)d_in[4];
    const float* b2 = (const float*)d_in[5];
    const float* Wf = (const float*)d_in[6];
    const float* bf = (const float*)d_in[7];
    float* out = (float*)d_out;

    int n = in_sizes[0] / IN_CH;   // 100000
    int E = in_sizes[1] / 2;       // 1600000

    // CSR build (by dst) + dense layer 1
    zero_cnt_kernel<<<(n + 255) / 256, 256>>>(n);
    hist_kernel<<<(E + 255) / 256, 256>>>(ei, E);
    scan_kernel<<<1, 1024>>>(n);
    fill_kernel<<<(E + 255) / 256, 256>>>(ei, E);
    dense1_kernel<<<(n + 255) / 256, 256>>>(nf, W1, b1, n);

    // Two atomic-free aggregation passes (warp per node)
    int ablocks = (n * 32 + 255) / 256;
    agg_kernel<0><<<ablocks, 256>>>(n);
    agg_kernel<1><<<ablocks, 256>>>(n);

    dense2_kernel<<<(n + 127) / 128, 128>>>(W2, b2, Wf, bf, out, n);
}